// round 14
// baseline (speedup 1.0000x reference)
#include <cuda_runtime.h>
#include <cuda_bf16.h>
#include <stdint.h>

#define BATCH  32
#define TFR    8
#define CDIM   768
#define CADIM  384
#define LTOK   196
#define LFULL  197
#define MROWS  (BATCH*TFR*LTOK)   // 50176

// Scratch — zero-init BSS device globals (no allocations allowed).
__device__ __nv_bfloat16 g_h1[(size_t)MROWS * CADIM];
__device__ __nv_bfloat16 g_h2[(size_t)MROWS * CADIM];
__device__ __nv_bfloat16 g_W1b[CADIM * CDIM];
__device__ __nv_bfloat16 g_W2b[CDIM * CADIM];

#define CP_ASYNC16(dst, src) \
    asm volatile("cp.async.cg.shared.global [%0], [%1], 16;\n" :: "r"(dst), "l"(src))
#define CP_COMMIT() asm volatile("cp.async.commit_group;\n")
#define CP_WAIT(n)  asm volatile("cp.async.wait_group %0;\n" :: "n"(n))

// ---------------------------------------------------------------------------
__global__ void cvt_weights(const float* __restrict__ W1, const float* __restrict__ W2) {
    int i = blockIdx.x * 256 + threadIdx.x;
    if (i < CADIM * CDIM) {
        g_W1b[i] = __float2bfloat16(W1[i]);
        g_W2b[i] = __float2bfloat16(W2[i]);
    }
}

__global__ void copy_cls(const float* __restrict__ x, float* __restrict__ out) {
    int i = blockIdx.x * 256 + threadIdx.x;
    if (i < BATCH * TFR * CDIM / 4) {
        int bt = i / (CDIM / 4), c4 = (i - bt * (CDIM / 4)) * 4;
        size_t off = (size_t)bt * LFULL * CDIM + c4;
        *(float4*)&out[off] = *(const float4*)&x[off];
    }
}

// ---------------------------------------------------------------------------
// GEMM compute core: warp tile 64x64, 4 warps (2x2) -> CTA 128x128.
// Per ks half: 8 B-x2 + 4 A-x4 ldmatrix, then 32 mma. Smem stride 40.
// ---------------------------------------------------------------------------
struct GemmFrag { float acc[4][8][4]; };

__device__ __forceinline__ void gemm_compute64(uint32_t asb, uint32_t bsb,
                                               int wm, int wn, int lane, GemmFrag& fr) {
#pragma unroll
    for (int ks = 0; ks < 2; ks++) {
        const int kk = ks * 16;
        uint32_t b[8][2];
#pragma unroll
        for (int nf = 0; nf < 8; nf++) {
            int row = wn * 64 + nf * 8 + (lane & 7);
            int col = kk + ((lane >> 3) & 1) * 8;
            uint32_t addr = bsb + (uint32_t)(row * 40 + col) * 2;
            asm volatile("ldmatrix.sync.aligned.m8n8.x2.shared.b16 {%0,%1}, [%2];\n"
                : "=r"(b[nf][0]), "=r"(b[nf][1]) : "r"(addr));
        }
        uint32_t a[4][4];
#pragma unroll
        for (int mf = 0; mf < 4; mf++) {
            int row = wm * 64 + mf * 16 + (lane & 15);
            int col = kk + (lane >> 4) * 8;
            uint32_t addr = asb + (uint32_t)(row * 40 + col) * 2;
            asm volatile("ldmatrix.sync.aligned.m8n8.x4.shared.b16 {%0,%1,%2,%3}, [%4];\n"
                : "=r"(a[mf][0]), "=r"(a[mf][1]), "=r"(a[mf][2]), "=r"(a[mf][3]) : "r"(addr));
        }
#pragma unroll
        for (int mf = 0; mf < 4; mf++)
#pragma unroll
            for (int nf = 0; nf < 8; nf++)
                asm volatile("mma.sync.aligned.m16n8k16.row.col.f32.bf16.bf16.f32 "
                    "{%0,%1,%2,%3}, {%4,%5,%6,%7}, {%8,%9}, {%0,%1,%2,%3};\n"
                    : "+f"(fr.acc[mf][nf][0]), "+f"(fr.acc[mf][nf][1]),
                      "+f"(fr.acc[mf][nf][2]), "+f"(fr.acc[mf][nf][3])
                    : "r"(a[mf][0]), "r"(a[mf][1]), "r"(a[mf][2]), "r"(a[mf][3]),
                      "r"(b[nf][0]), "r"(b[nf][1]));
    }
}

// ---------------------------------------------------------------------------
// GEMM1 (fused fp32->bf16): h1[M,384] = bf16( x_tok[M,768] @ W1^T + b1 )
// 128 threads. A: cp.async fp32 staging (3 stages) -> in-kernel bf16 convert.
// ---------------------------------------------------------------------------
#define AFSTR 36
#define AFB   (128 * AFSTR * 4)
#define TILB  (128 * 40 * 2)
#define SM_AF(s) ((s) * AFB)
#define SM_AS(p) (3 * AFB + (p) * TILB)
#define SM_BS(s) (3 * AFB + 2 * TILB + (s) * TILB)
#define G1_SMEM  (3 * AFB + 2 * TILB + 3 * TILB)

__global__ __launch_bounds__(128, 2)
void gemm1(const float* __restrict__ x, const float* __restrict__ b1) {
    extern __shared__ char smem[];
    const uint32_t sb = (uint32_t)__cvta_generic_to_shared(smem);

    const int tid  = threadIdx.x;
    const int lane = tid & 31;
    const int warp = tid >> 5;
    const int wm   = warp >> 1;
    const int wn   = warp & 1;
    const int bm   = (blockIdx.x / 3) * 128;
    const int bn   = (blockIdx.x % 3) * 128;

    // A fp32: thread owns full row tid (32 floats / k-chunk = 8 cp.16)
    size_t abase;
    {
        int grow = bm + tid;
        int bt = grow / LTOK, l = grow - bt * LTOK;
        abase = ((size_t)bt * LFULL + 1 + l) * CDIM;
    }
    const uint32_t af_dst = sb + (uint32_t)(tid * AFSTR) * 4;

    // B bf16: thread owns row tid (32 bf16 = 4 cp.16)
    const __nv_bfloat16* bptr = g_W1b + (size_t)(bn + tid) * CDIM;
    const uint32_t b_dst = sb + SM_BS(0) + (uint32_t)(tid * 40) * 2;

    GemmFrag fr;
#pragma unroll
    for (int i = 0; i < 4; i++)
#pragma unroll
        for (int j = 0; j < 8; j++)
#pragma unroll
            for (int k = 0; k < 4; k++) fr.acc[i][j][k] = 0.f;

    const int KT = CDIM / 32;   // 24

#define G1_ISSUE(s, k) do {                                                 \
        const uint32_t _ad = af_dst + (s) * AFB;                            \
        const float* _as = x + abase + (k) * 32;                            \
        _Pragma("unroll")                                                   \
        for (int j = 0; j < 8; j++) CP_ASYNC16(_ad + j * 16, _as + j * 4);  \
        const uint32_t _bd = b_dst + (s) * TILB;                            \
        const __nv_bfloat16* _bs = bptr + (k) * 32;                         \
        _Pragma("unroll")                                                   \
        for (int j = 0; j < 4; j++) CP_ASYNC16(_bd + j * 16, _bs + j * 8);  \
        CP_COMMIT();                                                        \
    } while (0)

    G1_ISSUE(0, 0);
    G1_ISSUE(1, 1);

    for (int k = 0; k < KT; k++) {
        const int s = k % 3, p = k & 1;
        CP_WAIT(1);
        __syncthreads();
        if (k + 2 < KT) G1_ISSUE((k + 2) % 3, k + 2);

        // convert AF[s] fp32 row -> As[p] bf16 row (thread = row tid)
        {
            const float* src = (const float*)(smem + SM_AF(s)) + tid * AFSTR;
            __nv_bfloat16* dst = (__nv_bfloat16*)(smem + SM_AS(p)) + tid * 40;
#pragma unroll
            for (int q = 0; q < 4; q++) {
                float4 f0 = *(const float4*)(src + q * 8);
                float4 f1 = *(const float4*)(src + q * 8 + 4);
                __nv_bfloat162 q0 = __floats2bfloat162_rn(f0.x, f0.y);
                __nv_bfloat162 q1 = __floats2bfloat162_rn(f0.z, f0.w);
                __nv_bfloat162 q2 = __floats2bfloat162_rn(f1.x, f1.y);
                __nv_bfloat162 q3 = __floats2bfloat162_rn(f1.z, f1.w);
                uint4 u;
                u.x = *(uint32_t*)&q0; u.y = *(uint32_t*)&q1;
                u.z = *(uint32_t*)&q2; u.w = *(uint32_t*)&q3;
                *(uint4*)(dst + q * 8) = u;
            }
        }
        __syncthreads();

        gemm_compute64(sb + SM_AS(p), sb + SM_BS(s), wm, wn, lane, fr);
    }

#pragma unroll
    for (int mf = 0; mf < 4; mf++) {
        int r0 = bm + wm * 64 + mf * 16 + (lane >> 2);
#pragma unroll
        for (int nf = 0; nf < 8; nf++) {
            int col = bn + wn * 64 + nf * 8 + (lane & 3) * 2;
            float bb0 = b1[col], bb1 = b1[col + 1];
            __nv_bfloat162 v0 = __floats2bfloat162_rn(fr.acc[mf][nf][0] + bb0, fr.acc[mf][nf][1] + bb1);
            __nv_bfloat162 v1 = __floats2bfloat162_rn(fr.acc[mf][nf][2] + bb0, fr.acc[mf][nf][3] + bb1);
            *(uint32_t*)&g_h1[(size_t)r0 * CADIM + col]       = *(uint32_t*)&v0;
            *(uint32_t*)&g_h1[(size_t)(r0 + 8) * CADIM + col] = *(uint32_t*)&v1;
        }
    }
}

// ---------------------------------------------------------------------------
// GEMM2: out_tok = x_tok + h2[M,384] @ W2^T + b2 (fp32, fused residual)
// 128 threads, 4-stage cp.async.
// ---------------------------------------------------------------------------
#define GSTAGES 4
#define GBUFB   (128 * 40 * 2)

__global__ __launch_bounds__(128, 2)
void gemm2(const float* __restrict__ x, const float* __restrict__ b2, float* __restrict__ out) {
    __shared__ __nv_bfloat16 As[GSTAGES][128 * 40];
    __shared__ __nv_bfloat16 Bs[GSTAGES][128 * 40];

    const int tid  = threadIdx.x;
    const int lane = tid & 31;
    const int warp = tid >> 5;
    const int wm   = warp >> 1;
    const int wn   = warp & 1;
    const int bm   = (blockIdx.x / 6) * 128;
    const int bn   = (blockIdx.x % 6) * 128;

    const __nv_bfloat16* aptr = g_h2  + (size_t)(bm + tid) * CADIM;
    const __nv_bfloat16* bptr = g_W2b + (size_t)(bn + tid) * CADIM;
    const uint32_t a_dst0 = (uint32_t)__cvta_generic_to_shared(&As[0][0]) + (uint32_t)(tid * 40) * 2;
    const uint32_t b_dst0 = (uint32_t)__cvta_generic_to_shared(&Bs[0][0]) + (uint32_t)(tid * 40) * 2;

    GemmFrag fr;
#pragma unroll
    for (int i = 0; i < 4; i++)
#pragma unroll
        for (int j = 0; j < 8; j++)
#pragma unroll
            for (int k = 0; k < 4; k++) fr.acc[i][j][k] = 0.f;

    const int KT = CADIM / 32;   // 12
#pragma unroll
    for (int s = 0; s < GSTAGES - 1; s++) {
#pragma unroll
        for (int j = 0; j < 4; j++) {
            CP_ASYNC16(a_dst0 + s * GBUFB + j * 16, aptr + s * 32 + j * 8);
            CP_ASYNC16(b_dst0 + s * GBUFB + j * 16, bptr + s * 32 + j * 8);
        }
        CP_COMMIT();
    }

    for (int k = 0; k < KT; k++) {
        CP_WAIT(GSTAGES - 2);
        __syncthreads();
        const int kn = k + GSTAGES - 1;
        if (kn < KT) {
            const int s = kn & (GSTAGES - 1);
#pragma unroll
            for (int j = 0; j < 4; j++) {
                CP_ASYNC16(a_dst0 + s * GBUFB + j * 16, aptr + kn * 32 + j * 8);
                CP_ASYNC16(b_dst0 + s * GBUFB + j * 16, bptr + kn * 32 + j * 8);
            }
        }
        CP_COMMIT();
        const int p = k & (GSTAGES - 1);
        gemm_compute64((uint32_t)__cvta_generic_to_shared(&As[0][0]) + p * GBUFB,
                       (uint32_t)__cvta_generic_to_shared(&Bs[0][0]) + p * GBUFB,
                       wm, wn, lane, fr);
    }

#pragma unroll
    for (int mf = 0; mf < 4; mf++) {
        int g0 = bm + wm * 64 + mf * 16 + (lane >> 2);
        int g1 = g0 + 8;
        int bt0 = g0 / LTOK, l0 = g0 - bt0 * LTOK;
        int bt1 = g1 / LTOK, l1 = g1 - bt1 * LTOK;
        size_t base0 = ((size_t)bt0 * LFULL + 1 + l0) * CDIM;
        size_t base1 = ((size_t)bt1 * LFULL + 1 + l1) * CDIM;
#pragma unroll
        for (int nf = 0; nf < 8; nf++) {
            int col = bn + wn * 64 + nf * 8 + (lane & 3) * 2;
            float bb0 = b2[col], bb1 = b2[col + 1];
            float2 x0 = *(const float2*)&x[base0 + col];
            float2 x1 = *(const float2*)&x[base1 + col];
            float2 o0, o1;
            o0.x = x0.x + fr.acc[mf][nf][0] + bb0;
            o0.y = x0.y + fr.acc[mf][nf][1] + bb1;
            o1.x = x1.x + fr.acc[mf][nf][2] + bb0;
            o1.y = x1.y + fr.acc[mf][nf][3] + bb1;
            *(float2*)&out[base0 + col] = o0;
            *(float2*)&out[base1 + col] = o1;
        }
    }
}

// ---------------------------------------------------------------------------
// Depthwise 3x3x3 conv — R9 version (measured 47.5us).
// ---------------------------------------------------------------------------
#define DW_TILE_W (6*16*17*8)            // 13056 words
#define DW_SMEM   ((DW_TILE_W + 216 + 8) * 4)
__global__ __launch_bounds__(224, 3)
void dwconv(const float* __restrict__ cw, const float* __restrict__ cb) {
    extern __shared__ uint32_t tile[];
    uint32_t* wsm = tile + DW_TILE_W;
    uint32_t* bsm = wsm + 216;

    const int tid = threadIdx.x;
    const int c0  = blockIdx.x * 16;
    const int b   = blockIdx.y;
    const int t0  = blockIdx.z * 4;

    uint4 z = make_uint4(0, 0, 0, 0);
    for (int i = tid; i < DW_TILE_W / 4; i += 224) ((uint4*)tile)[i] = z;

    for (int i = tid; i < 216; i += 224) {
        int j = i >> 3, cpp = i & 7, c = c0 + cpp * 2;
        __nv_bfloat162 wv = __floats2bfloat162_rn(cw[c * 27 + j], cw[(c + 1) * 27 + j]);
        wsm[i] = *(uint32_t*)&wv;
    }
    if (tid < 8) {
        int c = c0 + tid * 2;
        __nv_bfloat162 bv = __floats2bfloat162_rn(cb[c], cb[c + 1]);
        bsm[tid] = *(uint32_t*)&bv;
    }
    __syncthreads();

    for (int i = tid; i < 2352; i += 224) {
        int half = i & 1, pos = i >> 1;
        int tz = pos / 196, r = pos - tz * 196;
        int gt = t0 - 1 + tz;
        if ((unsigned)gt < 8u) {
            int hh = r / 14, ww = r - hh * 14;
            int word = ((tz * 16 + (hh + 1)) * 17 + (ww + 1)) * 8 + half * 4;
            uint4 v = *(const uint4*)&g_h1[((size_t)((b * 8 + gt) * 196 + r)) * CADIM + c0 + half * 8];
            *(uint4*)&tile[word] = v;
        }
    }

    const int cp    = tid & 7;
    const int rest  = tid >> 3;
    const int h     = rest % 14;
    const int tpair = rest / 14;

    uint32_t wk[27];
#pragma unroll
    for (int j = 0; j < 27; j++) wk[j] = wsm[j * 8 + cp];
    const uint32_t biasw = bsm[cp];

    __syncthreads();

#pragma unroll
    for (int tl = 0; tl < 2; tl++) {
        const int lt = tpair * 2 + tl;
        __nv_bfloat162 acc[14];
#pragma unroll
        for (int w = 0; w < 14; w++) acc[w] = *(__nv_bfloat162*)&biasw;

#pragma unroll
        for (int j = 0; j < 9; j++) {
            const int dt = j / 3, dh = j % 3;
            const int rb = (((lt + dt) * 16 + (h + dh)) * 17) * 8 + cp;
            uint32_t row[16];
#pragma unroll
            for (int xx = 0; xx < 16; xx++) row[xx] = tile[rb + xx * 8];
            const __nv_bfloat162 w0 = *(__nv_bfloat162*)&wk[j * 3 + 0];
            const __nv_bfloat162 w1 = *(__nv_bfloat162*)&wk[j * 3 + 1];
            const __nv_bfloat162 w2 = *(__nv_bfloat162*)&wk[j * 3 + 2];
#pragma unroll
            for (int w = 0; w < 14; w++) {
                acc[w] = __hfma2(*(__nv_bfloat162*)&row[w],     w0, acc[w]);
                acc[w] = __hfma2(*(__nv_bfloat162*)&row[w + 1], w1, acc[w]);
                acc[w] = __hfma2(*(__nv_bfloat162*)&row[w + 2], w2, acc[w]);
            }
        }

        size_t ob = ((size_t)((b * 8 + t0 + lt) * 196 + h * 14)) * CADIM + c0 + cp * 2;
#pragma unroll
        for (int w = 0; w < 14; w++)
            *(uint32_t*)&g_h2[ob + (size_t)w * CADIM] = *(uint32_t*)&acc[w];
    }
}

// ---------------------------------------------------------------------------
extern "C" void kernel_launch(void* const* d_in, const int* in_sizes, int n_in,
                              void* d_out, int out_size) {
    const float* x  = (const float*)d_in[0];
    const float* W1 = (const float*)d_in[1];
    const float* b1 = (const float*)d_in[2];
    const float* cw = (const float*)d_in[3];
    const float* cb = (const float*)d_in[4];
    const float* W2 = (const float*)d_in[5];
    const float* b2 = (const float*)d_in[6];
    float* out = (float*)d_out;

    static bool attr_done = false;
    if (!attr_done) {
        cudaFuncSetAttribute(dwconv, cudaFuncAttributeMaxDynamicSharedMemorySize, DW_SMEM);
        cudaFuncSetAttribute(gemm1,  cudaFuncAttributeMaxDynamicSharedMemorySize, G1_SMEM);
        attr_done = true;
    }

    cvt_weights<<<(CADIM * CDIM + 255) / 256, 256>>>(W1, W2);
    copy_cls<<<(BATCH * TFR * CDIM / 4 + 255) / 256, 256>>>(x, out);
    gemm1<<<(MROWS / 128) * 3, 128, G1_SMEM>>>(x, b1);
    dwconv<<<dim3(CADIM / 16, BATCH, 2), 224, DW_SMEM>>>(cw, cb);
    gemm2<<<(MROWS / 128) * 6, 128>>>(x, b2, out);
}

// round 16
// speedup vs baseline: 1.2519x; 1.2519x over previous
#include <cuda_runtime.h>
#include <cuda_fp16.h>
#include <stdint.h>

#define BATCH  32
#define TFR    8
#define CDIM   768
#define CADIM  384
#define LTOK   196
#define LFULL  197
#define MROWS  (BATCH*TFR*LTOK)   // 50176

// Scratch — zero-init BSS device globals (no allocations allowed).
__device__ __half g_h1[(size_t)MROWS * CADIM];
__device__ __half g_h2[(size_t)MROWS * CADIM];
__device__ __half g_W1h[CADIM * CDIM];
__device__ __half g_W2h[CDIM * CADIM];

#define CP_ASYNC16(dst, src) \
    asm volatile("cp.async.cg.shared.global [%0], [%1], 16;\n" :: "r"(dst), "l"(src))
#define CP_COMMIT() asm volatile("cp.async.commit_group;\n")
#define CP_WAIT(n)  asm volatile("cp.async.wait_group %0;\n" :: "n"(n))

// ---------------------------------------------------------------------------
__global__ void cvt_weights(const float* __restrict__ W1, const float* __restrict__ W2) {
    int i = blockIdx.x * 256 + threadIdx.x;
    if (i < CADIM * CDIM) {
        g_W1h[i] = __float2half(W1[i]);
        g_W2h[i] = __float2half(W2[i]);
    }
}

__global__ void copy_cls(const float* __restrict__ x, float* __restrict__ out) {
    int i = blockIdx.x * 256 + threadIdx.x;
    if (i < BATCH * TFR * CDIM / 4) {
        int bt = i / (CDIM / 4), c4 = (i - bt * (CDIM / 4)) * 4;
        size_t off = (size_t)bt * LFULL * CDIM + c4;
        *(float4*)&out[off] = *(const float4*)&x[off];
    }
}

// ---------------------------------------------------------------------------
// GEMM compute core: mma m16n8k16 f16 inputs + f16 accumulate (packed half2),
// warp 64x32, 8 warps (2x4) -> CTA 128x128.
// ---------------------------------------------------------------------------
struct GemmFrag { uint32_t acc[4][4][2]; };   // half2 accumulators

__device__ __forceinline__ void frag_zero(GemmFrag& fr) {
#pragma unroll
    for (int i = 0; i < 4; i++)
#pragma unroll
        for (int j = 0; j < 4; j++) { fr.acc[i][j][0] = 0u; fr.acc[i][j][1] = 0u; }
}

__device__ __forceinline__ void ldsm_a(uint32_t* r, uint32_t asb, int wm, int mf, int ks, int lane) {
    int row = wm * 64 + mf * 16 + (lane & 15);
    int col = ks * 16 + (lane >> 4) * 8;
    uint32_t addr = asb + (uint32_t)(row * 40 + col) * 2;
    asm volatile("ldmatrix.sync.aligned.m8n8.x4.shared.b16 {%0,%1,%2,%3}, [%4];\n"
        : "=r"(r[0]), "=r"(r[1]), "=r"(r[2]), "=r"(r[3]) : "r"(addr));
}

__device__ __forceinline__ void gemm_compute(uint32_t asb, uint32_t bsb,
                                             int wm, int wn, int lane, GemmFrag& fr) {
    uint32_t b[2][4][2];
#pragma unroll
    for (int ks = 0; ks < 2; ks++)
#pragma unroll
        for (int nf = 0; nf < 4; nf++) {
            int row = wn * 32 + nf * 8 + (lane & 7);
            int col = ks * 16 + ((lane >> 3) & 1) * 8;
            uint32_t addr = bsb + (uint32_t)(row * 40 + col) * 2;
            asm volatile("ldmatrix.sync.aligned.m8n8.x2.shared.b16 {%0,%1}, [%2];\n"
                : "=r"(b[ks][nf][0]), "=r"(b[ks][nf][1]) : "r"(addr));
        }
    uint32_t a[2][4];
    ldsm_a(a[0], asb, wm, 0, 0, lane);
#pragma unroll
    for (int step = 0; step < 8; step++) {
        const int ks = step >> 2, mf = step & 3;
        if (step < 7) {
            const int ns = step + 1;
            ldsm_a(a[ns & 1], asb, wm, ns & 3, ns >> 2, lane);
        }
        uint32_t* av = a[step & 1];
#pragma unroll
        for (int nf = 0; nf < 4; nf++)
            asm volatile("mma.sync.aligned.m16n8k16.row.col.f16.f16.f16.f16 "
                "{%0,%1}, {%2,%3,%4,%5}, {%6,%7}, {%0,%1};\n"
                : "+r"(fr.acc[mf][nf][0]), "+r"(fr.acc[mf][nf][1])
                : "r"(av[0]), "r"(av[1]), "r"(av[2]), "r"(av[3]),
                  "r"(b[ks][nf][0]), "r"(b[ks][nf][1]));
    }
}

// ---------------------------------------------------------------------------
// GEMM1 (fused fp32->fp16): h1[M,384] = fp16( x_tok[M,768] @ W1^T + b1 )
// ---------------------------------------------------------------------------
#define AFSTR 36
#define AFB   (128 * AFSTR * 4)
#define TILB  (128 * 40 * 2)
#define SM_AF(s) ((s) * AFB)
#define SM_AS(p) (3 * AFB + (p) * TILB)
#define SM_BS(s) (3 * AFB + 2 * TILB + (s) * TILB)
#define G1_SMEM  (3 * AFB + 2 * TILB + 3 * TILB)

__global__ __launch_bounds__(256, 2)
void gemm1(const float* __restrict__ x, const float* __restrict__ b1) {
    extern __shared__ char smem[];
    const uint32_t sb = (uint32_t)__cvta_generic_to_shared(smem);

    const int tid  = threadIdx.x;
    const int lane = tid & 31;
    const int warp = tid >> 5;
    const int wm   = warp >> 2;
    const int wn   = warp & 3;
    const int bm   = (blockIdx.x / 3) * 128;
    const int bn   = (blockIdx.x % 3) * 128;

    const int ar  = tid >> 3;
    const int acf = (tid & 7) * 4;
    size_t abase[4];
#pragma unroll
    for (int j = 0; j < 4; j++) {
        int grow = bm + ar + 32 * j;
        int bt = grow / LTOK, l = grow - bt * LTOK;
        abase[j] = ((size_t)bt * LFULL + 1 + l) * CDIM + acf;
    }
    const uint32_t af_dst = sb + (uint32_t)(ar * AFSTR + acf) * 4;

    const int brow = tid >> 1, bcol = (tid & 1) * 16;
    const __half* bptr = g_W1h + (size_t)(bn + brow) * CDIM + bcol;
    const uint32_t b_dst = sb + SM_BS(0) + (uint32_t)(brow * 40 + bcol) * 2;

    GemmFrag fr;
    frag_zero(fr);

    const int KT = CDIM / 32;   // 24

#define G1_ISSUE(s, k) do {                                                 \
        const uint32_t _ad = af_dst + (s) * AFB;                            \
        _Pragma("unroll")                                                   \
        for (int j = 0; j < 4; j++)                                         \
            CP_ASYNC16(_ad + j * 32 * AFSTR * 4, x + abase[j] + (k) * 32);  \
        const uint32_t _bd = b_dst + (s) * TILB;                            \
        CP_ASYNC16(_bd,      bptr + (k) * 32);                              \
        CP_ASYNC16(_bd + 16, bptr + (k) * 32 + 8);                          \
        CP_COMMIT();                                                        \
    } while (0)

    G1_ISSUE(0, 0);
    G1_ISSUE(1, 1);

    const int crow = tid >> 1, ccol = (tid & 1) * 16;

    for (int k = 0; k < KT; k++) {
        const int s = k % 3, p = k & 1;
        CP_WAIT(1);
        __syncthreads();
        if (k + 2 < KT) G1_ISSUE((k + 2) % 3, k + 2);

        {
            const float* src = (const float*)(smem + SM_AF(s)) + crow * AFSTR + ccol;
            float4 f0 = *(const float4*)(src);
            float4 f1 = *(const float4*)(src + 4);
            float4 f2 = *(const float4*)(src + 8);
            float4 f3 = *(const float4*)(src + 12);
            __half2 q0 = __floats2half2_rn(f0.x, f0.y);
            __half2 q1 = __floats2half2_rn(f0.z, f0.w);
            __half2 q2 = __floats2half2_rn(f1.x, f1.y);
            __half2 q3 = __floats2half2_rn(f1.z, f1.w);
            __half2 q4 = __floats2half2_rn(f2.x, f2.y);
            __half2 q5 = __floats2half2_rn(f2.z, f2.w);
            __half2 q6 = __floats2half2_rn(f3.x, f3.y);
            __half2 q7 = __floats2half2_rn(f3.z, f3.w);
            uint4 u0, u1;
            u0.x = *(uint32_t*)&q0; u0.y = *(uint32_t*)&q1;
            u0.z = *(uint32_t*)&q2; u0.w = *(uint32_t*)&q3;
            u1.x = *(uint32_t*)&q4; u1.y = *(uint32_t*)&q5;
            u1.z = *(uint32_t*)&q6; u1.w = *(uint32_t*)&q7;
            __half* dst = (__half*)(smem + SM_AS(p)) + crow * 40 + ccol;
            *(uint4*)dst       = u0;
            *(uint4*)(dst + 8) = u1;
        }
        __syncthreads();

        gemm_compute(sb + SM_AS(p), sb + SM_BS(s), wm, wn, lane, fr);
    }

#pragma unroll
    for (int mf = 0; mf < 4; mf++) {
        int r0 = bm + wm * 64 + mf * 16 + (lane >> 2);
#pragma unroll
        for (int nf = 0; nf < 4; nf++) {
            int col = bn + wn * 32 + nf * 8 + (lane & 3) * 2;
            __half2 bias2 = __floats2half2_rn(b1[col], b1[col + 1]);
            __half2 v0 = __hadd2(*(__half2*)&fr.acc[mf][nf][0], bias2);
            __half2 v1 = __hadd2(*(__half2*)&fr.acc[mf][nf][1], bias2);
            *(uint32_t*)&g_h1[(size_t)r0 * CADIM + col]       = *(uint32_t*)&v0;
            *(uint32_t*)&g_h1[(size_t)(r0 + 8) * CADIM + col] = *(uint32_t*)&v1;
        }
    }
}

// ---------------------------------------------------------------------------
// GEMM2: out_tok = x_tok + h2[M,384] @ W2^T + b2 (fp32 out, fused residual)
// ---------------------------------------------------------------------------
#define GSTAGES 4
#define GBUFB   (128 * 40 * 2)

__global__ __launch_bounds__(256, 2)
void gemm2(const float* __restrict__ x, const float* __restrict__ b2, float* __restrict__ out) {
    __shared__ __half As[GSTAGES][128 * 40];
    __shared__ __half Bs[GSTAGES][128 * 40];

    const int tid  = threadIdx.x;
    const int lane = tid & 31;
    const int warp = tid >> 5;
    const int wm   = warp >> 2;
    const int wn   = warp & 3;
    const int bm   = (blockIdx.x / 6) * 128;
    const int bn   = (blockIdx.x % 6) * 128;

    const int row  = tid >> 1;
    const int col0 = (tid & 1) * 16;
    const __half* aptr = g_h2  + (size_t)(bm + row) * CADIM + col0;
    const __half* bptr = g_W2h + (size_t)(bn + row) * CADIM + col0;
    const uint32_t a_dst0 = (uint32_t)__cvta_generic_to_shared(&As[0][0]) + (uint32_t)(row * 40 + col0) * 2;
    const uint32_t b_dst0 = (uint32_t)__cvta_generic_to_shared(&Bs[0][0]) + (uint32_t)(row * 40 + col0) * 2;

    GemmFrag fr;
    frag_zero(fr);

    const int KT = CADIM / 32;   // 12
#pragma unroll
    for (int s = 0; s < GSTAGES - 1; s++) {
        CP_ASYNC16(a_dst0 + s * GBUFB,      aptr + s * 32);
        CP_ASYNC16(a_dst0 + s * GBUFB + 16, aptr + s * 32 + 8);
        CP_ASYNC16(b_dst0 + s * GBUFB,      bptr + s * 32);
        CP_ASYNC16(b_dst0 + s * GBUFB + 16, bptr + s * 32 + 8);
        CP_COMMIT();
    }

    for (int k = 0; k < KT; k++) {
        CP_WAIT(GSTAGES - 2);
        __syncthreads();
        const int kn = k + GSTAGES - 1;
        if (kn < KT) {
            const int s = kn & (GSTAGES - 1);
            CP_ASYNC16(a_dst0 + s * GBUFB,      aptr + kn * 32);
            CP_ASYNC16(a_dst0 + s * GBUFB + 16, aptr + kn * 32 + 8);
            CP_ASYNC16(b_dst0 + s * GBUFB,      bptr + kn * 32);
            CP_ASYNC16(b_dst0 + s * GBUFB + 16, bptr + kn * 32 + 8);
        }
        CP_COMMIT();
        const int p = k & (GSTAGES - 1);
        gemm_compute((uint32_t)__cvta_generic_to_shared(&As[0][0]) + p * GBUFB,
                     (uint32_t)__cvta_generic_to_shared(&Bs[0][0]) + p * GBUFB,
                     wm, wn, lane, fr);
    }

#pragma unroll
    for (int mf = 0; mf < 4; mf++) {
        int g0 = bm + wm * 64 + mf * 16 + (lane >> 2);
        int g1 = g0 + 8;
        int bt0 = g0 / LTOK, l0 = g0 - bt0 * LTOK;
        int bt1 = g1 / LTOK, l1 = g1 - bt1 * LTOK;
        size_t base0 = ((size_t)bt0 * LFULL + 1 + l0) * CDIM;
        size_t base1 = ((size_t)bt1 * LFULL + 1 + l1) * CDIM;
#pragma unroll
        for (int nf = 0; nf < 4; nf++) {
            int col = bn + wn * 32 + nf * 8 + (lane & 3) * 2;
            float bb0 = b2[col], bb1 = b2[col + 1];
            float2 h0 = __half22float2(*(__half2*)&fr.acc[mf][nf][0]);
            float2 h1v = __half22float2(*(__half2*)&fr.acc[mf][nf][1]);
            float2 x0 = *(const float2*)&x[base0 + col];
            float2 x1 = *(const float2*)&x[base1 + col];
            float2 o0, o1;
            o0.x = x0.x + h0.x + bb0;
            o0.y = x0.y + h0.y + bb1;
            o1.x = x1.x + h1v.x + bb0;
            o1.y = x1.y + h1v.y + bb1;
            *(float2*)&out[base0 + col] = o0;
            *(float2*)&out[base1 + col] = o1;
        }
    }
}

// ---------------------------------------------------------------------------
// Depthwise 3x3x3 conv — R9 structure, fp16 types.
// ---------------------------------------------------------------------------
#define DW_TILE_W (6*16*17*8)            // 13056 words
#define DW_SMEM   ((DW_TILE_W + 216 + 8) * 4)
__global__ __launch_bounds__(224, 3)
void dwconv(const float* __restrict__ cw, const float* __restrict__ cb) {
    extern __shared__ uint32_t tile[];
    uint32_t* wsm = tile + DW_TILE_W;
    uint32_t* bsm = wsm + 216;

    const int tid = threadIdx.x;
    const int c0  = blockIdx.x * 16;
    const int b   = blockIdx.y;
    const int t0  = blockIdx.z * 4;

    uint4 z = make_uint4(0, 0, 0, 0);
    for (int i = tid; i < DW_TILE_W / 4; i += 224) ((uint4*)tile)[i] = z;

    for (int i = tid; i < 216; i += 224) {
        int j = i >> 3, cpp = i & 7, c = c0 + cpp * 2;
        __half2 wv = __floats2half2_rn(cw[c * 27 + j], cw[(c + 1) * 27 + j]);
        wsm[i] = *(uint32_t*)&wv;
    }
    if (tid < 8) {
        int c = c0 + tid * 2;
        __half2 bv = __floats2half2_rn(cb[c], cb[c + 1]);
        bsm[tid] = *(uint32_t*)&bv;
    }
    __syncthreads();

    for (int i = tid; i < 2352; i += 224) {
        int half = i & 1, pos = i >> 1;
        int tz = pos / 196, r = pos - tz * 196;
        int gt = t0 - 1 + tz;
        if ((unsigned)gt < 8u) {
            int hh = r / 14, ww = r - hh * 14;
            int word = ((tz * 16 + (hh + 1)) * 17 + (ww + 1)) * 8 + half * 4;
            uint4 v = *(const uint4*)&g_h1[((size_t)((b * 8 + gt) * 196 + r)) * CADIM + c0 + half * 8];
            *(uint4*)&tile[word] = v;
        }
    }

    const int cp    = tid & 7;
    const int rest  = tid >> 3;
    const int h     = rest % 14;
    const int tpair = rest / 14;

    uint32_t wk[27];
#pragma unroll
    for (int j = 0; j < 27; j++) wk[j] = wsm[j * 8 + cp];
    const uint32_t biasw = bsm[cp];

    __syncthreads();

#pragma unroll
    for (int tl = 0; tl < 2; tl++) {
        const int lt = tpair * 2 + tl;
        __half2 acc[14];
#pragma unroll
        for (int w = 0; w < 14; w++) acc[w] = *(__half2*)&biasw;

#pragma unroll
        for (int j = 0; j < 9; j++) {
            const int dt = j / 3, dh = j % 3;
            const int rb = (((lt + dt) * 16 + (h + dh)) * 17) * 8 + cp;
            uint32_t row[16];
#pragma unroll
            for (int xx = 0; xx < 16; xx++) row[xx] = tile[rb + xx * 8];
            const __half2 w0 = *(__half2*)&wk[j * 3 + 0];
            const __half2 w1 = *(__half2*)&wk[j * 3 + 1];
            const __half2 w2 = *(__half2*)&wk[j * 3 + 2];
#pragma unroll
            for (int w = 0; w < 14; w++) {
                acc[w] = __hfma2(*(__half2*)&row[w],     w0, acc[w]);
                acc[w] = __hfma2(*(__half2*)&row[w + 1], w1, acc[w]);
                acc[w] = __hfma2(*(__half2*)&row[w + 2], w2, acc[w]);
            }
        }

        size_t ob = ((size_t)((b * 8 + t0 + lt) * 196 + h * 14)) * CADIM + c0 + cp * 2;
#pragma unroll
        for (int w = 0; w < 14; w++)
            *(uint32_t*)&g_h2[ob + (size_t)w * CADIM] = *(uint32_t*)&acc[w];
    }
}

// ---------------------------------------------------------------------------
extern "C" void kernel_launch(void* const* d_in, const int* in_sizes, int n_in,
                              void* d_out, int out_size) {
    const float* x  = (const float*)d_in[0];
    const float* W1 = (const float*)d_in[1];
    const float* b1 = (const float*)d_in[2];
    const float* cw = (const float*)d_in[3];
    const float* cb = (const float*)d_in[4];
    const float* W2 = (const float*)d_in[5];
    const float* b2 = (const float*)d_in[6];
    float* out = (float*)d_out;

    static bool attr_done = false;
    if (!attr_done) {
        cudaFuncSetAttribute(dwconv, cudaFuncAttributeMaxDynamicSharedMemorySize, DW_SMEM);
        cudaFuncSetAttribute(gemm1,  cudaFuncAttributeMaxDynamicSharedMemorySize, G1_SMEM);
        attr_done = true;
    }

    cvt_weights<<<(CADIM * CDIM + 255) / 256, 256>>>(W1, W2);
    copy_cls<<<(BATCH * TFR * CDIM / 4 + 255) / 256, 256>>>(x, out);
    gemm1<<<(MROWS / 128) * 3, 256, G1_SMEM>>>(x, b1);
    dwconv<<<dim3(CADIM / 16, BATCH, 2), 224, DW_SMEM>>>(cw, cb);
    gemm2<<<(MROWS / 128) * 6, 256>>>(x, b2, out);
}